// round 9
// baseline (speedup 1.0000x reference)
#include <cuda_runtime.h>
#include <mma.h>
#include <cstddef>
#include <cstdint>

using namespace nvcuda;

#define BB 64
#define TT 512
#define DD 512
#define HH 768
#define NG 3072
#define MMROWS (BB * TT)
#define NCTA 96
#define NCTA_DIR 48

#define WS_LD 66                  // 768 x 66 floats = 202752 B
#define HS_LD 36                  // stage row: 32 + 4 pad
#define GS_LD 68
#define HS_OFF 202752
#define STAGE_B 9216              // 64 * 36 * 4
#define TAILOFF 230400            // bias + mbarriers
#define SMEM_REC 230912

__device__ float g_xp[(size_t)2 * MMROWS * NG];
__device__ float g_h[2][2][BB * HH];
__device__ unsigned g_bar_count[2];
__device__ unsigned g_bar_gen[2];

__device__ __forceinline__ float sigmoidf(float x) {
    return 1.0f / (1.0f + __expf(-x));
}
__device__ __forceinline__ uint32_t smem_u32(const void* p) {
    uint32_t a;
    asm("{ .reg .u64 t; cvta.to.shared.u64 t, %1; cvt.u32.u64 %0, t; }" : "=r"(a) : "l"(p));
    return a;
}

#define MBARRIER_INIT(addr, cnt) \
    asm volatile("mbarrier.init.shared.b64 [%0], %1;" :: "r"(addr), "r"(cnt) : "memory")
#define MBARRIER_ARRIVE(addr) \
    asm volatile("mbarrier.arrive.shared.b64 _, [%0];" :: "r"(addr) : "memory")
#define MBARRIER_WAIT_PARITY(addr, par) do {                                   \
    asm volatile(                                                              \
        "{\n\t.reg .pred P1;\n\t"                                              \
        "WL_%=:\n\t"                                                           \
        "mbarrier.try_wait.parity.acquire.cta.shared::cta.b64 P1, [%0], %1, 0x989680;\n\t" \
        "@P1 bra.uni WD_%=;\n\t"                                               \
        "bra.uni WL_%=;\n\t"                                                   \
        "WD_%=:\n\t}"                                                          \
        :: "r"(addr), "r"((uint32_t)(par)) : "memory");                        \
} while (0)

__device__ __forceinline__ unsigned bar_arrive(int dir) {
    unsigned gen = *((volatile unsigned*)&g_bar_gen[dir]);
    __threadfence();
    unsigned arr = atomicAdd(&g_bar_count[dir], 1u);
    if (arr == NCTA_DIR - 1) {
        g_bar_count[dir] = 0;
        __threadfence();
        atomicAdd(&g_bar_gen[dir], 1u);
    }
    return gen;
}
__device__ __forceinline__ void bar_wait(int dir, unsigned gen) {
    int spins = 0;
    while (*((volatile unsigned*)&g_bar_gen[dir]) == gen) {
        if (++spins > 64) __nanosleep(20);
    }
    __threadfence();
}

// ---------------------------------------------------------------------------
// xproj (unchanged, known-good)
// ---------------------------------------------------------------------------
__global__ void __launch_bounds__(256) xproj_kernel(
    const float* __restrict__ seq,
    const float* __restrict__ Wfw,
    const float* __restrict__ Wbw)
{
    const int dir = blockIdx.z;
    const float* W = dir ? Wbw : Wfw;
    float* xp = g_xp + (size_t)dir * MMROWS * NG;
    const int m0 = blockIdx.x * 128;
    const int n0 = blockIdx.y * 64;

    __shared__ __align__(16) float As[128][20];
    __shared__ __align__(16) float Bs[16][68];

    const int tid = threadIdx.x;
    const int w = tid >> 5, wm = w & 3, wn = w >> 2;

    wmma::fragment<wmma::accumulator, 16, 16, 8, float> acc[2][2];
#pragma unroll
    for (int i = 0; i < 2; i++)
#pragma unroll
        for (int j = 0; j < 2; j++) wmma::fill_fragment(acc[i][j], 0.0f);

    float ra[8], rb[4];
#pragma unroll
    for (int e = 0; e < 8; e++) {
        int idx = e * 256 + tid; int r = idx >> 4, c = idx & 15;
        ra[e] = seq[(size_t)(m0 + r) * DD + c];
    }
#pragma unroll
    for (int e = 0; e < 4; e++) {
        int idx = e * 256 + tid; int r = idx >> 6, c = idx & 63;
        rb[e] = W[(size_t)r * NG + n0 + c];
    }

    for (int kt = 0; kt < DD / 16; kt++) {
        __syncthreads();
#pragma unroll
        for (int e = 0; e < 8; e++) {
            int idx = e * 256 + tid; int r = idx >> 4, c = idx & 15;
            As[r][c] = ra[e];
        }
#pragma unroll
        for (int e = 0; e < 4; e++) {
            int idx = e * 256 + tid; int r = idx >> 6, c = idx & 63;
            Bs[r][c] = rb[e];
        }
        __syncthreads();
        if (kt + 1 < DD / 16) {
            int k0 = (kt + 1) * 16;
#pragma unroll
            for (int e = 0; e < 8; e++) {
                int idx = e * 256 + tid; int r = idx >> 4, c = idx & 15;
                ra[e] = seq[(size_t)(m0 + r) * DD + k0 + c];
            }
#pragma unroll
            for (int e = 0; e < 4; e++) {
                int idx = e * 256 + tid; int r = idx >> 6, c = idx & 63;
                rb[e] = W[(size_t)(k0 + r) * NG + n0 + c];
            }
        }
#pragma unroll
        for (int k8 = 0; k8 < 16; k8 += 8) {
            wmma::fragment<wmma::matrix_a, 16, 16, 8, wmma::precision::tf32, wmma::row_major> af[2];
            wmma::fragment<wmma::matrix_b, 16, 16, 8, wmma::precision::tf32, wmma::row_major> bf[2];
#pragma unroll
            for (int fm = 0; fm < 2; fm++) {
                wmma::load_matrix_sync(af[fm], &As[wm * 32 + fm * 16][k8], 20);
#pragma unroll
                for (int i = 0; i < af[fm].num_elements; i++)
                    af[fm].x[i] = wmma::__float_to_tf32(af[fm].x[i]);
            }
#pragma unroll
            for (int fn = 0; fn < 2; fn++) {
                wmma::load_matrix_sync(bf[fn], &Bs[k8][wn * 32 + fn * 16], 68);
#pragma unroll
                for (int i = 0; i < bf[fn].num_elements; i++)
                    bf[fn].x[i] = wmma::__float_to_tf32(bf[fn].x[i]);
            }
#pragma unroll
            for (int fm = 0; fm < 2; fm++)
#pragma unroll
                for (int fn = 0; fn < 2; fn++)
                    wmma::mma_sync(acc[fm][fn], af[fm], bf[fn], acc[fm][fn]);
        }
    }
#pragma unroll
    for (int fm = 0; fm < 2; fm++)
#pragma unroll
        for (int fn = 0; fn < 2; fn++) {
            size_t row = m0 + wm * 32 + fm * 16;
            size_t col = n0 + wn * 32 + fn * 16;
            wmma::store_matrix_sync(xp + row * NG + col, acc[fm][fn], NG,
                                    wmma::mem_row_major);
        }
}

__device__ __forceinline__ void cp16s(uint32_t smem_dst, const float* gmem_src) {
    asm volatile("cp.async.ca.shared.global [%0], [%1], 16;\n"
                 :: "r"(smem_dst), "l"(gmem_src));
}

// ---------------------------------------------------------------------------
// Persistent recurrence: warp-specialized mbarrier pipeline.
// warps 0-7 consume (WMMA, 2 tiles each), warps 8-15 produce (cp.async h).
// ---------------------------------------------------------------------------
__global__ void __launch_bounds__(512, 1) lstm_persistent(
    const int* __restrict__ seq_len,
    const float* __restrict__ Wfw, const float* __restrict__ bfw,
    const float* __restrict__ Wbw, const float* __restrict__ bbw,
    float* __restrict__ out)
{
    const int dir = blockIdx.x / 48;
    const int jb  = blockIdx.x % 48;
    const float* W    = dir ? Wbw : Wfw;
    const float* bias = dir ? bbw : bfw;
    const float* xp = g_xp + (size_t)dir * MMROWS * NG;

    extern __shared__ __align__(16) char sm[];
    const uint32_t smb = smem_u32(sm);
    float* Ws = (float*)sm;                          // [768][WS_LD]
    float* Gs = (float*)(sm + HS_OFF);               // overlay on stages
    float* bs = (float*)(sm + TAILOFF);              // 64 floats
    const uint32_t mb_full[3]  = { smb + TAILOFF + 256, smb + TAILOFF + 264,
                                   smb + TAILOFF + 272 };
    const uint32_t mb_empty[3] = { smb + TAILOFF + 280, smb + TAILOFF + 288,
                                   smb + TAILOFF + 296 };
    __shared__ unsigned s_gen;

    const int tid = threadIdx.x;
    const int w = tid >> 5;
    const bool is_cons = (w < 8);

    // one-time: W slice (tf32-rounded) into Ws
    for (int i = tid; i < 768 * 64; i += 512) {
        int k = i >> 6, n = i & 63;
        int g = n >> 4, c = n & 15;
        Ws[k * WS_LD + n] = wmma::__float_to_tf32(
            W[(size_t)(DD + k) * NG + g * HH + jb * 16 + c]);
    }
    if (tid < 64) {
        int g = tid >> 4, c = tid & 15;
        bs[tid] = bias[g * HH + jb * 16 + c];
    }
    if (tid == 0) {
#pragma unroll
        for (int s = 0; s < 3; s++) {
            MBARRIER_INIT(mb_full[s], 256);
            MBARRIER_INIT(mb_empty[s], 256);
        }
    }

    // per-thread cell ownership (update tail, all 512 threads)
    const int j  = tid & 15;
    const int jg = jb * 16 + j;
    const int bb0 = tid >> 4;
    const int bb1 = bb0 + 32;
    const int L0 = seq_len[bb0];
    const int L1 = seq_len[bb1];
    float c0 = 0.f, c1 = 0.f, h0 = 0.f, h1 = 0.f;
    g_h[dir][0][bb0 * HH + jg] = 0.f;
    g_h[dir][0][bb1 * HH + jg] = 0.f;

    // consumer mapping: warp cw covers m-blocks {2*wp, 2*wp+1}, n-block wn
    const int wn = w & 3;
    const int wp = (w >> 2) & 1;

    // producer mapping: 256 threads, 2 adjacent 16B units each
    const int ptid = tid & 255;
    const int prow = ptid >> 2;              // 0..63
    const int pu   = (ptid & 3) * 2;         // 0,2,4,6
    const uint32_t pdst0 = smb + HS_OFF + (uint32_t)(prow * HS_LD * 4 + pu * 16);
    const int psrc = prow * HH + pu * 4;

    int phF[3] = {0, 0, 0};    // consumer full phases
    int phE[3] = {0, 0, 0};    // producer empty phases

    __syncthreads();
    if (tid == 0) { unsigned g0 = bar_arrive(dir); bar_wait(dir, g0); }
    __syncthreads();

    for (int t = 0; t < TT; t++) {
        const int parr = t & 1;
        const float* hsrc = g_h[dir][parr];
        float* hdst = g_h[dir][parr ^ 1];

        const bool a0 = t < L0, a1 = t < L1;
        const int tx0 = dir ? (a0 ? L0 - 1 - t : t) : t;
        const int tx1 = dir ? (a1 ? L1 - 1 - t : t) : t;
        const float* x0 = xp + ((size_t)bb0 * TT + tx0) * NG + jg;
        const float* x1 = xp + ((size_t)bb1 * TT + tx1) * NG + jg;
        float xv00 = x0[0], xv01 = x0[HH], xv02 = x0[2 * HH], xv03 = x0[3 * HH];
        float xv10 = x1[0], xv11 = x1[HH], xv12 = x1[2 * HH], xv13 = x1[3 * HH];

        wmma::fragment<wmma::accumulator, 16, 16, 8, float> acc0, acc1;

        if (is_cons) {
            wmma::fill_fragment(acc0, 0.f);
            wmma::fill_fragment(acc1, 0.f);
            for (int ck = 0; ck < 24; ck++) {
                const int s = ck % 3;
                MBARRIER_WAIT_PARITY(mb_full[s], phF[s]);
                phF[s] ^= 1;
                const float* Hst = (float*)(sm + HS_OFF + s * STAGE_B);
#pragma unroll
                for (int k8 = 0; k8 < 4; k8++) {
                    wmma::fragment<wmma::matrix_a, 16, 16, 8, wmma::precision::tf32, wmma::row_major> af0, af1;
                    wmma::fragment<wmma::matrix_b, 16, 16, 8, wmma::precision::tf32, wmma::row_major> bf;
                    wmma::load_matrix_sync(af0, Hst + (wp * 32) * HS_LD + k8 * 8, HS_LD);
                    wmma::load_matrix_sync(af1, Hst + (wp * 32 + 16) * HS_LD + k8 * 8, HS_LD);
                    wmma::load_matrix_sync(bf, Ws + (ck * 32 + k8 * 8) * WS_LD + wn * 16, WS_LD);
                    wmma::mma_sync(acc0, af0, bf, acc0);
                    wmma::mma_sync(acc1, af1, bf, acc1);
                }
                MBARRIER_ARRIVE(mb_empty[s]);
            }
        } else {
            for (int ck = 0; ck < 24; ck++) {
                const int s = ck % 3;
                if (t > 0 || ck >= 3) {
                    MBARRIER_WAIT_PARITY(mb_empty[s], phE[s]);
                    phE[s] ^= 1;
                }
                const float* src = hsrc + psrc + ck * 32;
                const uint32_t dst = pdst0 + (uint32_t)(s * STAGE_B);
                cp16s(dst, src);
                cp16s(dst + 16, src + 4);
                asm volatile("cp.async.commit_group;\n");
                if (ck >= 2) {
                    asm volatile("cp.async.wait_group 2;\n");
                    MBARRIER_ARRIVE(mb_full[(ck - 2) % 3]);
                }
            }
            asm volatile("cp.async.wait_group 1;\n");
            MBARRIER_ARRIVE(mb_full[1]);               // ck = 22
            asm volatile("cp.async.wait_group 0;\n");
            MBARRIER_ARRIVE(mb_full[2]);               // ck = 23
        }

        __syncthreads();   // all MMAs done everywhere; stages reusable as Gs
        if (is_cons) {
            wmma::store_matrix_sync(Gs + (wp * 32) * GS_LD + wn * 16, acc0,
                                    GS_LD, wmma::mem_row_major);
            wmma::store_matrix_sync(Gs + (wp * 32 + 16) * GS_LD + wn * 16, acc1,
                                    GS_LD, wmma::mem_row_major);
        }
        __syncthreads();

        float nh0, nh1;
        {
            float gi = Gs[bb0 * GS_LD +  0 + j] + xv00 + bs[j];
            float gj = Gs[bb0 * GS_LD + 16 + j] + xv01 + bs[16 + j];
            float gf = Gs[bb0 * GS_LD + 32 + j] + xv02 + bs[32 + j];
            float go = Gs[bb0 * GS_LD + 48 + j] + xv03 + bs[48 + j];
            float nc = c0 * sigmoidf(gf + 1.f) + sigmoidf(gi) * tanhf(gj);
            nh0 = tanhf(nc) * sigmoidf(go);
            if (a0) { c0 = nc; h0 = nh0; }
            hdst[bb0 * HH + jg] = wmma::__float_to_tf32(h0);
        }
        {
            float gi = Gs[bb1 * GS_LD +  0 + j] + xv10 + bs[j];
            float gj = Gs[bb1 * GS_LD + 16 + j] + xv11 + bs[16 + j];
            float gf = Gs[bb1 * GS_LD + 32 + j] + xv12 + bs[32 + j];
            float go = Gs[bb1 * GS_LD + 48 + j] + xv13 + bs[48 + j];
            float nc = c1 * sigmoidf(gf + 1.f) + sigmoidf(gi) * tanhf(gj);
            nh1 = tanhf(nc) * sigmoidf(go);
            if (a1) { c1 = nc; h1 = nh1; }
            hdst[bb1 * HH + jg] = wmma::__float_to_tf32(h1);
        }

        __syncthreads();                        // Gs reads done; h stores issued
        if (tid == 0) s_gen = bar_arrive(dir);  // fence covers h stores only
        {
            int to0 = (dir && a0) ? (L0 - 1 - t) : t;
            out[((size_t)bb0 * TT + to0) * (2 * HH) + dir * HH + jg] = a0 ? nh0 : 0.f;
            int to1 = (dir && a1) ? (L1 - 1 - t) : t;
            out[((size_t)bb1 * TT + to1) * (2 * HH) + dir * HH + jg] = a1 ? nh1 : 0.f;
        }
        if (tid == 0) bar_wait(dir, s_gen);
        __syncthreads();
    }

    out[(size_t)BB * TT * 2 * HH + (size_t)bb0 * 2 * HH + dir * HH + jg] = h0;
    out[(size_t)BB * TT * 2 * HH + (size_t)bb1 * 2 * HH + dir * HH + jg] = h1;
}

// ---------------------------------------------------------------------------
extern "C" void kernel_launch(void* const* d_in, const int* in_sizes, int n_in,
                              void* d_out, int out_size)
{
    const float* seq     = (const float*)d_in[0];
    const int*   seq_len = (const int*)d_in[1];
    const float* Wfw     = (const float*)d_in[2];
    const float* bfw     = (const float*)d_in[3];
    const float* Wbw     = (const float*)d_in[4];
    const float* bbw     = (const float*)d_in[5];
    float* out = (float*)d_out;

    cudaFuncSetAttribute(lstm_persistent,
                         cudaFuncAttributeMaxDynamicSharedMemorySize, SMEM_REC);

    xproj_kernel<<<dim3(MMROWS / 128, NG / 64, 2), 256>>>(seq, Wfw, Wbw);

    lstm_persistent<<<NCTA, 512, SMEM_REC>>>(seq_len, Wfw, bfw, Wbw, bbw, out);
}